// round 16
// baseline (speedup 1.0000x reference)
#include <cuda_runtime.h>
#include <cuda_bf16.h>

#define VOCAB 32000
#define EMBED 32
#define HID   16
#define SEQ   128
#define BATCH 32
#define G4    64
#define NCHUNK 32      // 1024-vocab chunks per timestep
#define NCONS  288     // persistent consumer blocks = 32 chunks x 9 t-lanes
#define TSTRIDE 9      // t advance per step (NCONS/NCHUNK)

// ---------------- scratch (device globals; no allocation) ----------------
__device__ float g_XG[SEQ * G4 * BATCH];   // [t][gate*HID+u][b]
__device__ float g_H [SEQ * HID * BATCH];  // [t][k][b]
__device__ float g_rowsum[SEQ * BATCH];
__device__ unsigned g_flagH[SEQ];
__device__ unsigned g_cnt[SEQ];

// ---------------- helpers ----------------
__device__ __forceinline__ unsigned long long pk2(float lo, float hi) {
    unsigned long long r;
    asm("mov.b64 %0, {%1, %2};" : "=l"(r) : "f"(lo), "f"(hi));
    return r;
}
__device__ __forceinline__ unsigned long long fma2(unsigned long long a,
                                                   unsigned long long b,
                                                   unsigned long long c) {
    unsigned long long d;
    asm("fma.rn.f32x2 %0, %1, %2, %3;" : "=l"(d) : "l"(a), "l"(b), "l"(c));
    return d;
}
__device__ __forceinline__ float hsum2(unsigned long long v) {
    float lo, hi;
    asm("mov.b64 {%0, %1}, %2;" : "=f"(lo), "=f"(hi) : "l"(v));
    return lo + hi;
}
__device__ __forceinline__ float tanha(float x) {
    float y;
    asm("tanh.approx.f32 %0, %1;" : "=f"(y) : "f"(x));
    return y;
}
__device__ __forceinline__ float sgm(float x) {
    return fmaf(tanha(0.5f * x), 0.5f, 0.5f);
}
__device__ __forceinline__ unsigned ld_acq(const unsigned* p) {
    unsigned v;
    asm volatile("ld.acquire.gpu.u32 %0, [%1];" : "=r"(v) : "l"(p) : "memory");
    return v;
}
__device__ __forceinline__ float ld_acq_f(const float* p) {
    float v;
    asm volatile("ld.acquire.gpu.f32 %0, [%1];" : "=f"(v) : "l"(p) : "memory");
    return v;
}
__device__ __forceinline__ void stcs4(float* p, float4 v) {
    asm volatile("st.global.cs.v4.f32 [%0], {%1, %2, %3, %4};"
                 :: "l"(p), "f"(v.x), "f"(v.y), "f"(v.z), "f"(v.w) : "memory");
}

// ---------------- K1: input-side gate preacts + scratch reset --------------
__global__ __launch_bounds__(256) void k1_xgates(
    const int* __restrict__ idx, const float* __restrict__ emb,
    const float* __restrict__ Wih, const float* __restrict__ bih,
    const float* __restrict__ bhh) {
    __shared__ float xs[BATCH][EMBED + 1];
    __shared__ float ws[G4][EMBED];
    __shared__ float bias[G4];
    const int t = blockIdx.x, tid = threadIdx.x;

    if (tid == 0) { g_flagH[t] = 0u; g_cnt[t] = 0u; }
    if (tid < BATCH) g_rowsum[t * BATCH + tid] = 0.f;

    for (int i = tid; i < BATCH * EMBED; i += 256) {
        int b = i >> 5, e = i & 31;
        xs[b][e] = emb[idx[t * BATCH + b] * EMBED + e];
    }
    for (int i = tid; i < G4 * EMBED; i += 256) ws[i >> 5][i & 31] = Wih[i];
    if (tid < G4) bias[tid] = bih[tid] + bhh[tid];
    __syncthreads();

    for (int i = tid; i < G4 * BATCH; i += 256) {
        int j = i >> 5, b = i & 31;
        float acc = bias[j];
#pragma unroll
        for (int e = 0; e < EMBED; e++) acc = fmaf(xs[b][e], ws[j][e], acc);
        g_XG[(t * G4 + j) * BATCH + b] = acc;
    }
}

// ---- fused: producer (block 0) + persistent consumers w/ deferred fixup ---
__global__ __launch_bounds__(256, 2) void k_fused(
    const float* __restrict__ Whh, const float* __restrict__ h0,
    const float* __restrict__ c0,  const float* __restrict__ Wout,
    const float* __restrict__ bout, float* __restrict__ out) {
    const int tid = threadIdx.x;

    if (blockIdx.x == 0) {
        // ============ producer: LSTM recurrence ============
        const int u = tid >> 4, l = tid & 15;
        const int b0 = l, b1 = l + 16;
        __shared__ float hs[2][HID][BATCH];
        __shared__ unsigned long long wp[4][HID][8];

        for (int i = tid; i < 4 * HID * 8; i += 256) {
            int g = i >> 7, rest = i & 127, uu = rest >> 3, p = rest & 7;
            const float* row = Whh + (g * HID + uu) * HID;
            wp[g][uu][p] = pk2(row[2 * p], row[2 * p + 1]);
        }
        for (int i = tid; i < HID * BATCH; i += 256) {
            int uu = i >> 5, b = i & 31;
            hs[0][uu][b] = h0[b * HID + uu];
        }
        float cc0 = c0[b0 * HID + u], cc1 = c0[b1 * HID + u];

        float xgn0[4], xgn1[4];
#pragma unroll
        for (int g = 0; g < 4; g++) {
            xgn0[g] = g_XG[(g * HID + u) * BATCH + b0];
            xgn1[g] = g_XG[(g * HID + u) * BATCH + b1];
        }
        __syncthreads();

        int cur = 0;
        for (int t = 0; t < SEQ; t++) {
            float xg0[4], xg1[4];
#pragma unroll
            for (int g = 0; g < 4; g++) { xg0[g] = xgn0[g]; xg1[g] = xgn1[g]; }
            if (t + 1 < SEQ) {
                const float* base = g_XG + (t + 1) * G4 * BATCH;
#pragma unroll
                for (int g = 0; g < 4; g++) {
                    xgn0[g] = base[(g * HID + u) * BATCH + b0];
                    xgn1[g] = base[(g * HID + u) * BATCH + b1];
                }
            }
            unsigned long long h2a[8], h2b[8];
#pragma unroll
            for (int p = 0; p < 8; p++) {
                h2a[p] = pk2(hs[cur][2 * p][b0], hs[cur][2 * p + 1][b0]);
                h2b[p] = pk2(hs[cur][2 * p][b1], hs[cur][2 * p + 1][b1]);
            }
            float ga[4], gb[4];
#pragma unroll
            for (int g = 0; g < 4; g++) {
                unsigned long long a0 = 0ull, a1 = 0ull;
#pragma unroll
                for (int p = 0; p < 8; p++) {
                    unsigned long long w = wp[g][u][p];
                    a0 = fma2(w, h2a[p], a0);
                    a1 = fma2(w, h2b[p], a1);
                }
                ga[g] = hsum2(a0) + xg0[g];
                gb[g] = hsum2(a1) + xg1[g];
            }
            float hn0, hn1;
            {
                float ii = sgm(ga[0]), ff = sgm(ga[1]);
                float gg = tanha(ga[2]), oo = sgm(ga[3]);
                cc0 = ff * cc0 + ii * gg;
                hn0 = oo * tanha(cc0);
            }
            {
                float ii = sgm(gb[0]), ff = sgm(gb[1]);
                float gg = tanha(gb[2]), oo = sgm(gb[3]);
                cc1 = ff * cc1 + ii * gg;
                hn1 = oo * tanha(cc1);
            }
            hs[cur ^ 1][u][b0] = hn0;
            hs[cur ^ 1][u][b1] = hn1;
            float* gh = g_H + t * (HID * BATCH);
            gh[u * BATCH + b0] = hn0;
            gh[u * BATCH + b1] = hn1;
            __syncthreads();
            if (tid == 0) { __threadfence(); atomicExch(&g_flagH[t], 1u); }
            cur ^= 1;
        }
        return;
    }

    // ========== persistent consumers: fixed chunk, sweep t by TSTRIDE ======
    const int j     = blockIdx.x - 1;        // 0..NCONS-1
    const int chunk = j & (NCHUNK - 1);
    const int t0    = j >> 5;                // 0..8
    const int v0    = chunk * 1024 + 4 * tid;
    const bool ok   = v0 < VOCAB;

    // 4 weight rows resident in registers for the block's whole life
    unsigned long long w[4][8];
    float bb[4];
    if (ok) {
        const float4* wv = (const float4*)(Wout + (size_t)v0 * HID);
#pragma unroll
        for (int r = 0; r < 4; r++) {
#pragma unroll
            for (int q = 0; q < 4; q++) {
                float4 f = wv[r * 4 + q];
                w[r][2 * q] = pk2(f.x, f.y);
                w[r][2 * q + 1] = pk2(f.z, f.w);
            }
            bb[r] = bout[v0 + r];
        }
    } else {
#pragma unroll
        for (int r = 0; r < 4; r++) {
#pragma unroll
            for (int p = 0; p < 8; p++) w[r][p] = 0ull;
            bb[r] = 0.f;
        }
    }

    __shared__ __align__(16) unsigned long long h2s[BATCH][8];
    __shared__ float bsum[BATCH];
    __shared__ float lseS[BATCH];

    // double-buffered per-thread logit cache (local memory)
    float4 lbuf[2][BATCH];

    const int lane = tid & 31;
    int buf = 0;
    int t_prev = -1;

    for (int t = t0; t < SEQ; t += TSTRIDE) {
        // ---- wait for h(t) (producer only) ----
        if (tid == 0) {
            while (ld_acq(&g_flagH[t]) == 0u) __nanosleep(32);
        }
        __syncthreads();
        {
            int b = tid >> 3, p = tid & 7;
            const float* gh = g_H + t * (HID * BATCH);
            h2s[b][p] = pk2(__ldcg(gh + (2 * p) * BATCH + b),
                            __ldcg(gh + (2 * p + 1) * BATCH + b));
        }
        if (tid < BATCH) bsum[tid] = 0.f;
        __syncthreads();

        // ---- K3: logits -> lbuf[buf], exp-sums -> rowsum ----
#pragma unroll 1
        for (int b4 = 0; b4 < BATCH; b4 += 4) {
            float e[4];
#pragma unroll
            for (int i = 0; i < 4; i++) {
                const unsigned long long* h2b = h2s[b4 + i];
                unsigned long long a0 = pk2(bb[0], 0.f);
                unsigned long long a1 = pk2(bb[1], 0.f);
                unsigned long long a2 = pk2(bb[2], 0.f);
                unsigned long long a3 = pk2(bb[3], 0.f);
#pragma unroll
                for (int p = 0; p < 8; p++) {
                    unsigned long long h = h2b[p];
                    a0 = fma2(w[0][p], h, a0);
                    a1 = fma2(w[1][p], h, a1);
                    a2 = fma2(w[2][p], h, a2);
                    a3 = fma2(w[3][p], h, a3);
                }
                float4 v;
                v.x = hsum2(a0); v.y = hsum2(a1);
                v.z = hsum2(a2); v.w = hsum2(a3);
                lbuf[buf][b4 + i] = v;
                e[i] = ok ? (__expf(v.x) + __expf(v.y) +
                             __expf(v.z) + __expf(v.w)) : 0.f;
            }
            float e0 = e[0], e1 = e[1], e2 = e[2], e3 = e[3];
#pragma unroll
            for (int m = 16; m > 0; m >>= 1) {
                e0 += __shfl_xor_sync(0xffffffffu, e0, m);
                e1 += __shfl_xor_sync(0xffffffffu, e1, m);
                e2 += __shfl_xor_sync(0xffffffffu, e2, m);
                e3 += __shfl_xor_sync(0xffffffffu, e3, m);
            }
            if (lane == 0) {
                atomicAdd(&bsum[b4 + 0], e0);
                atomicAdd(&bsum[b4 + 1], e1);
                atomicAdd(&bsum[b4 + 2], e2);
                atomicAdd(&bsum[b4 + 3], e3);
            }
        }
        __syncthreads();
        if (tid < BATCH) {
            atomicAdd(&g_rowsum[t * BATCH + tid], bsum[tid]);
            __threadfence();
        }
        __syncthreads();
        if (tid == 0) atomicAdd(&g_cnt[t], 1u);

        // ---- deferred K4 for t_prev (one step of slack -> near-zero spin) --
        if (t_prev >= 0) {
            if (tid == 0) {
                while (ld_acq(&g_cnt[t_prev]) < (unsigned)NCHUNK) __nanosleep(32);
            }
            __syncthreads();
            if (tid < BATCH)
                lseS[tid] = __logf(ld_acq_f(&g_rowsum[t_prev * BATCH + tid]));
            __syncthreads();
            if (ok) {
                float* orow = out + ((size_t)t_prev * BATCH) * VOCAB + v0;
#pragma unroll 2
                for (int b = 0; b < BATCH; b++) {
                    float L = lseS[b];
                    float4 v = lbuf[buf ^ 1][b];
                    float4 o;
                    o.x = v.x - L; o.y = v.y - L;
                    o.z = v.z - L; o.w = v.w - L;
                    stcs4(orow + (size_t)b * VOCAB, o);
                }
            }
        }
        t_prev = t;
        buf ^= 1;
    }

    // ---- epilogue: K4 for the final tile ----
    if (t_prev >= 0) {
        if (tid == 0) {
            while (ld_acq(&g_cnt[t_prev]) < (unsigned)NCHUNK) __nanosleep(32);
        }
        __syncthreads();
        if (tid < BATCH)
            lseS[tid] = __logf(ld_acq_f(&g_rowsum[t_prev * BATCH + tid]));
        __syncthreads();
        if (ok) {
            float* orow = out + ((size_t)t_prev * BATCH) * VOCAB + v0;
#pragma unroll 2
            for (int b = 0; b < BATCH; b++) {
                float L = lseS[b];
                float4 v = lbuf[buf ^ 1][b];
                float4 o;
                o.x = v.x - L; o.y = v.y - L;
                o.z = v.z - L; o.w = v.w - L;
                stcs4(orow + (size_t)b * VOCAB, o);
            }
        }
    }
}

// ---------------- launch ----------------
extern "C" void kernel_launch(void* const* d_in, const int* in_sizes, int n_in,
                              void* d_out, int out_size) {
    const int*   idx  = (const int*)  d_in[0];
    const float* emb  = (const float*)d_in[1];
    const float* Wih  = (const float*)d_in[2];
    const float* Whh  = (const float*)d_in[3];
    const float* bih  = (const float*)d_in[4];
    const float* bhh  = (const float*)d_in[5];
    const float* Wout = (const float*)d_in[6];
    const float* bout = (const float*)d_in[7];
    const float* h0   = (const float*)d_in[8];
    const float* c0   = (const float*)d_in[9];
    float* out = (float*)d_out;

    k1_xgates<<<SEQ, 256>>>(idx, emb, Wih, bih, bhh);
    k_fused<<<1 + NCONS, 256>>>(Whh, h0, c0, Wout, bout, out);
}

// round 17
// speedup vs baseline: 1.2512x; 1.2512x over previous
#include <cuda_runtime.h>
#include <cuda_bf16.h>
#include <cuda_fp16.h>

#define VOCAB 32000
#define EMBED 32
#define HID   16
#define SEQ   128
#define BATCH 32
#define G4    64
#define NCHUNK 32      // 1024-vocab chunks per timestep

// ---------------- scratch (device globals; no allocation) ----------------
__device__ float g_XG[SEQ * G4 * BATCH];   // [t][gate*HID+u][b]
__device__ float g_H [SEQ * HID * BATCH];  // [t][k][b]
__device__ float g_rowsum[SEQ * BATCH];
__device__ unsigned g_flagH[SEQ];
__device__ unsigned g_cnt[SEQ];

// ---------------- helpers ----------------
__device__ __forceinline__ unsigned long long pk2(float lo, float hi) {
    unsigned long long r;
    asm("mov.b64 %0, {%1, %2};" : "=l"(r) : "f"(lo), "f"(hi));
    return r;
}
__device__ __forceinline__ unsigned long long fma2(unsigned long long a,
                                                   unsigned long long b,
                                                   unsigned long long c) {
    unsigned long long d;
    asm("fma.rn.f32x2 %0, %1, %2, %3;" : "=l"(d) : "l"(a), "l"(b), "l"(c));
    return d;
}
__device__ __forceinline__ float hsum2(unsigned long long v) {
    float lo, hi;
    asm("mov.b64 {%0, %1}, %2;" : "=f"(lo), "=f"(hi) : "l"(v));
    return lo + hi;
}
__device__ __forceinline__ float tanha(float x) {
    float y;
    asm("tanh.approx.f32 %0, %1;" : "=f"(y) : "f"(x));
    return y;
}
__device__ __forceinline__ float sgm(float x) {
    return fmaf(tanha(0.5f * x), 0.5f, 0.5f);
}
__device__ __forceinline__ unsigned ld_acq(const unsigned* p) {
    unsigned v;
    asm volatile("ld.acquire.gpu.u32 %0, [%1];" : "=r"(v) : "l"(p) : "memory");
    return v;
}
__device__ __forceinline__ float ld_acq_f(const float* p) {
    float v;
    asm volatile("ld.acquire.gpu.f32 %0, [%1];" : "=f"(v) : "l"(p) : "memory");
    return v;
}
__device__ __forceinline__ void stcs4(float* p, float4 v) {
    asm volatile("st.global.cs.v4.f32 [%0], {%1, %2, %3, %4};"
                 :: "l"(p), "f"(v.x), "f"(v.y), "f"(v.z), "f"(v.w) : "memory");
}
// pack two f32 into f16x2 (lo in low half)
__device__ __forceinline__ unsigned pkh2(float lo, float hi) {
    unsigned r;
    asm("cvt.rn.f16x2.f32 %0, %1, %2;" : "=r"(r) : "f"(hi), "f"(lo));
    return r;
}
// unpack f16x2 to two f32
__device__ __forceinline__ float2 uph2(unsigned u) {
    float lo, hi;
    asm("{.reg .f16 a, b;\n\t"
        "mov.b32 {a, b}, %2;\n\t"
        "cvt.f32.f16 %0, a;\n\t"
        "cvt.f32.f16 %1, b;}"
        : "=f"(lo), "=f"(hi) : "r"(u));
    return make_float2(lo, hi);
}

// ---------------- K1: input-side gate preacts + scratch reset --------------
__global__ __launch_bounds__(256) void k1_xgates(
    const int* __restrict__ idx, const float* __restrict__ emb,
    const float* __restrict__ Wih, const float* __restrict__ bih,
    const float* __restrict__ bhh) {
    __shared__ float xs[BATCH][EMBED + 1];
    __shared__ float ws[G4][EMBED];
    __shared__ float bias[G4];
    const int t = blockIdx.x, tid = threadIdx.x;

    if (tid == 0) { g_flagH[t] = 0u; g_cnt[t] = 0u; }
    if (tid < BATCH) g_rowsum[t * BATCH + tid] = 0.f;

    for (int i = tid; i < BATCH * EMBED; i += 256) {
        int b = i >> 5, e = i & 31;
        xs[b][e] = emb[idx[t * BATCH + b] * EMBED + e];
    }
    for (int i = tid; i < G4 * EMBED; i += 256) ws[i >> 5][i & 31] = Wih[i];
    if (tid < G4) bias[tid] = bih[tid] + bhh[tid];
    __syncthreads();

    for (int i = tid; i < G4 * BATCH; i += 256) {
        int j = i >> 5, b = i & 31;
        float acc = bias[j];
#pragma unroll
        for (int e = 0; e < EMBED; e++) acc = fmaf(xs[b][e], ws[j][e], acc);
        g_XG[(t * G4 + j) * BATCH + b] = acc;
    }
}

// ---- fused: producer (block 0) + consumers: K3 (f16 logit cache) + K4 -----
__global__ __launch_bounds__(256, 2) void k_fused(
    const float* __restrict__ Whh, const float* __restrict__ h0,
    const float* __restrict__ c0,  const float* __restrict__ Wout,
    const float* __restrict__ bout, float* __restrict__ out) {
    const int tid = threadIdx.x;

    if (blockIdx.x == 0) {
        // ============ producer: LSTM recurrence ============
        const int u = tid >> 4, l = tid & 15;
        const int b0 = l, b1 = l + 16;
        __shared__ float hs[2][HID][BATCH];
        __shared__ unsigned long long wp[4][HID][8];

        for (int i = tid; i < 4 * HID * 8; i += 256) {
            int g = i >> 7, rest = i & 127, uu = rest >> 3, p = rest & 7;
            const float* row = Whh + (g * HID + uu) * HID;
            wp[g][uu][p] = pk2(row[2 * p], row[2 * p + 1]);
        }
        for (int i = tid; i < HID * BATCH; i += 256) {
            int uu = i >> 5, b = i & 31;
            hs[0][uu][b] = h0[b * HID + uu];
        }
        float cc0 = c0[b0 * HID + u], cc1 = c0[b1 * HID + u];

        float xgn0[4], xgn1[4];
#pragma unroll
        for (int g = 0; g < 4; g++) {
            xgn0[g] = g_XG[(g * HID + u) * BATCH + b0];
            xgn1[g] = g_XG[(g * HID + u) * BATCH + b1];
        }
        __syncthreads();

        int cur = 0;
        for (int t = 0; t < SEQ; t++) {
            float xg0[4], xg1[4];
#pragma unroll
            for (int g = 0; g < 4; g++) { xg0[g] = xgn0[g]; xg1[g] = xgn1[g]; }
            if (t + 1 < SEQ) {
                const float* base = g_XG + (t + 1) * G4 * BATCH;
#pragma unroll
                for (int g = 0; g < 4; g++) {
                    xgn0[g] = base[(g * HID + u) * BATCH + b0];
                    xgn1[g] = base[(g * HID + u) * BATCH + b1];
                }
            }
            unsigned long long h2a[8], h2b[8];
#pragma unroll
            for (int p = 0; p < 8; p++) {
                h2a[p] = pk2(hs[cur][2 * p][b0], hs[cur][2 * p + 1][b0]);
                h2b[p] = pk2(hs[cur][2 * p][b1], hs[cur][2 * p + 1][b1]);
            }
            float ga[4], gb[4];
#pragma unroll
            for (int g = 0; g < 4; g++) {
                unsigned long long a0 = 0ull, a1 = 0ull;
#pragma unroll
                for (int p = 0; p < 8; p++) {
                    unsigned long long w = wp[g][u][p];
                    a0 = fma2(w, h2a[p], a0);
                    a1 = fma2(w, h2b[p], a1);
                }
                ga[g] = hsum2(a0) + xg0[g];
                gb[g] = hsum2(a1) + xg1[g];
            }
            float hn0, hn1;
            {
                float ii = sgm(ga[0]), ff = sgm(ga[1]);
                float gg = tanha(ga[2]), oo = sgm(ga[3]);
                cc0 = ff * cc0 + ii * gg;
                hn0 = oo * tanha(cc0);
            }
            {
                float ii = sgm(gb[0]), ff = sgm(gb[1]);
                float gg = tanha(gb[2]), oo = sgm(gb[3]);
                cc1 = ff * cc1 + ii * gg;
                hn1 = oo * tanha(cc1);
            }
            hs[cur ^ 1][u][b0] = hn0;
            hs[cur ^ 1][u][b1] = hn1;
            float* gh = g_H + t * (HID * BATCH);
            gh[u * BATCH + b0] = hn0;
            gh[u * BATCH + b1] = hn1;
            __syncthreads();
            if (tid == 0) { __threadfence(); atomicExch(&g_flagH[t], 1u); }
            cur ^= 1;
        }
        return;
    }

    // ============ consumers: K3 (f16x2 logit cache), then K4 ===============
    const int bid   = blockIdx.x - 1;
    const int t     = bid >> 5;            // ascending with block index
    const int chunk = bid & (NCHUNK - 1);
    const int v0    = chunk * 1024 + 4 * tid;
    const bool ok   = v0 < VOCAB;

    // 4 weight rows resident in registers
    unsigned long long w[4][8];
    float bb[4];
    if (ok) {
        const float4* wv = (const float4*)(Wout + (size_t)v0 * HID);
#pragma unroll
        for (int r = 0; r < 4; r++) {
#pragma unroll
            for (int q = 0; q < 4; q++) {
                float4 f = wv[r * 4 + q];
                w[r][2 * q] = pk2(f.x, f.y);
                w[r][2 * q + 1] = pk2(f.z, f.w);
            }
            bb[r] = bout[v0 + r];
        }
    } else {
#pragma unroll
        for (int r = 0; r < 4; r++) {
#pragma unroll
            for (int p = 0; p < 8; p++) w[r][p] = 0ull;
            bb[r] = 0.f;
        }
    }

    __shared__ __align__(16) unsigned long long h2s[BATCH][8];
    __shared__ float bsum[BATCH];
    __shared__ float lseS[BATCH];

    // per-thread logit cache: 32 x f16x2-pair = 256 B local (L1-resident)
    uint2 lbuf[BATCH];

    // ---- wait for h(t) (producer only; always ahead) ----
    if (tid == 0) {
        while (ld_acq(&g_flagH[t]) == 0u) __nanosleep(32);
    }
    __syncthreads();
    {
        int b = tid >> 3, p = tid & 7;
        const float* gh = g_H + t * (HID * BATCH);
        h2s[b][p] = pk2(__ldcg(gh + (2 * p) * BATCH + b),
                        __ldcg(gh + (2 * p + 1) * BATCH + b));
    }
    if (tid < BATCH) bsum[tid] = 0.f;
    __syncthreads();

    // ---- K3: logits -> f16 local cache, sum of exps -> rowsum ----
    const int lane = tid & 31;
#pragma unroll 1
    for (int b4 = 0; b4 < BATCH; b4 += 4) {
        float e[4];
#pragma unroll
        for (int i = 0; i < 4; i++) {
            const unsigned long long* h2b = h2s[b4 + i];
            unsigned long long a0 = pk2(bb[0], 0.f);
            unsigned long long a1 = pk2(bb[1], 0.f);
            unsigned long long a2 = pk2(bb[2], 0.f);
            unsigned long long a3 = pk2(bb[3], 0.f);
#pragma unroll
            for (int p = 0; p < 8; p++) {
                unsigned long long h = h2b[p];
                a0 = fma2(w[0][p], h, a0);
                a1 = fma2(w[1][p], h, a1);
                a2 = fma2(w[2][p], h, a2);
                a3 = fma2(w[3][p], h, a3);
            }
            float v0f = hsum2(a0), v1f = hsum2(a1);
            float v2f = hsum2(a2), v3f = hsum2(a3);
            lbuf[b4 + i] = make_uint2(pkh2(v0f, v1f), pkh2(v2f, v3f)); // STL.64
            e[i] = ok ? (__expf(v0f) + __expf(v1f) +
                         __expf(v2f) + __expf(v3f)) : 0.f;
        }
        float e0 = e[0], e1 = e[1], e2 = e[2], e3 = e[3];
#pragma unroll
        for (int m = 16; m > 0; m >>= 1) {
            e0 += __shfl_xor_sync(0xffffffffu, e0, m);
            e1 += __shfl_xor_sync(0xffffffffu, e1, m);
            e2 += __shfl_xor_sync(0xffffffffu, e2, m);
            e3 += __shfl_xor_sync(0xffffffffu, e3, m);
        }
        if (lane == 0) {
            atomicAdd(&bsum[b4 + 0], e0);
            atomicAdd(&bsum[b4 + 1], e1);
            atomicAdd(&bsum[b4 + 2], e2);
            atomicAdd(&bsum[b4 + 3], e3);
        }
    }
    __syncthreads();
    if (tid < BATCH) {
        atomicAdd(&g_rowsum[t * BATCH + tid], bsum[tid]);
        __threadfence();
    }
    __syncthreads();

    // ---- rendezvous: all 32 chunks of this t done with K3 ----
    if (tid == 0) {
        atomicAdd(&g_cnt[t], 1u);
        while (ld_acq(&g_cnt[t]) < (unsigned)NCHUNK) __nanosleep(32);
    }
    __syncthreads();
    if (tid < BATCH) lseS[tid] = __logf(ld_acq_f(&g_rowsum[t * BATCH + tid]));
    __syncthreads();

    // ---- K4: read cached f16 logits, subtract lse, streaming store ----
    if (!ok) return;
    float* orow = out + ((size_t)t * BATCH) * VOCAB + v0;
#pragma unroll 2
    for (int b = 0; b < BATCH; b++) {
        float L = lseS[b];
        uint2 u = lbuf[b];                           // LDL.64 (L1-hit)
        float2 v01 = uph2(u.x);
        float2 v23 = uph2(u.y);
        float4 o;
        o.x = v01.x - L; o.y = v01.y - L;
        o.z = v23.x - L; o.w = v23.y - L;
        stcs4(orow + (size_t)b * VOCAB, o);
    }
}

// ---------------- launch ----------------
extern "C" void kernel_launch(void* const* d_in, const int* in_sizes, int n_in,
                              void* d_out, int out_size) {
    const int*   idx  = (const int*)  d_in[0];
    const float* emb  = (const float*)d_in[1];
    const float* Wih  = (const float*)d_in[2];
    const float* Whh  = (const float*)d_in[3];
    const float* bih  = (const float*)d_in[4];
    const float* bhh  = (const float*)d_in[5];
    const float* Wout = (const float*)d_in[6];
    const float* bout = (const float*)d_in[7];
    const float* h0   = (const float*)d_in[8];
    const float* c0   = (const float*)d_in[9];
    float* out = (float*)d_out;

    k1_xgates<<<SEQ, 256>>>(idx, emb, Wih, bih, bhh);
    k_fused<<<1 + SEQ * NCHUNK, 256>>>(Whh, h0, c0, Wout, bout, out);
}